// round 16
// baseline (speedup 1.0000x reference)
#include <cuda_runtime.h>
#include <cuda_bf16.h>
#include <stdint.h>

// x: (16, 256, 32, 16, 11) fp32 ; part_labels: (16, 32, 16, 11) int64 (or int32)
// out: (16, 256, 32, 16) fp32
#define N_   16
#define C_   256
#define S_   32
#define HW_  176
#define P_   16
#define NS_  (N_ * S_)

#define THREADS  256
#define CH_BLK   32
#define CGRPS    (C_ / CH_BLK)     // 8
#define RSTF     177               // odd -> conflict-free gather
#define NEG_FILL -100.0f

__device__ __forceinline__ void cpa4(uint32_t dst, const float* src) {
    asm volatile("cp.async.ca.shared.global [%0], [%1], 4;" :: "r"(dst), "l"(src));
}
__device__ __forceinline__ void cpa_commit() {
    asm volatile("cp.async.commit_group;");
}
__device__ __forceinline__ void cpa_wait0() {
    asm volatile("cp.async.wait_group 0;");
}
// pinned-order global load (volatile asm keeps order vs the cp.async asm)
__device__ __forceinline__ int ldg_ord(const int* p) {
    int v; asm volatile("ld.global.u32 %0, [%1];" : "=r"(v) : "l"(p)); return v;
}

__global__ __launch_bounds__(THREADS, 8)
void hpp_kernel(const float* __restrict__ x,
                const int*   __restrict__ lbl32,
                float*       __restrict__ out)
{
    __shared__ float         s_tile[CH_BLK * RSTF];   // 22.7 KB
    __shared__ float         s_res[CH_BLK * 17];
    __shared__ unsigned      s_pk[64];                // compact padded index lists
    __shared__ unsigned char s_startW[P_];
    __shared__ int           s_cnt[P_];
    __shared__ float         s_inv[P_];
    __shared__ unsigned char s_order[P_];
    __shared__ int           s_wcnt[6 * P_];

    const int ns   = blockIdx.x;
    const int n_i  = ns >> 5;
    const int s_i  = ns & 31;
    const int chb  = blockIdx.y * CH_BLK;
    const int tid  = threadIdx.x;
    const int wid  = tid >> 5;
    const int lane = tid & 31;

    const float* xbase = x + (((size_t)n_i * C_ + chb) * S_ + s_i) * HW_;

    // ---- 1) is64 probe FIRST (independent, L2-hot, per-warp — no barrier) ----
    int probe = ldg_ord(lbl32 + 2 * lane + 1);   // first 64 words of label buffer

    // ---- 2) tile staging immediately after (before the ballot stalls) ----
    #pragma unroll
    for (int r = 0; r < 4; r++) {
        const int row = wid * 4 + r;
        const float* src = xbase + (size_t)row * (S_ * HW_);
        uint32_t dsh = (uint32_t)__cvta_generic_to_shared(s_tile + row * RSTF);
        #pragma unroll
        for (int k = 0; k < 6; k++) {
            int j = lane + 32 * k;
            if (j < HW_) cpa4(dsh + 4u * j, src + j);
        }
    }
    cpa_commit();

    // zero shared counters while loads fly
    if (tid < 6 * P_) s_wcnt[tid] = 0;
    if (tid < 64) s_pk[tid] = 0u;

    // ---- 3) per-warp is64 resolve + single predicated label load ----
    const bool is64 = (__ballot_sync(0xFFFFFFFFu, probe == 0) == 0xFFFFFFFFu);
    int mylbl = -1;
    if (tid < HW_) {
        int idx = ns * HW_ + tid;
        mylbl = ldg_ord(lbl32 + (is64 ? 2 * idx : idx));
    }
    __syncthreads();                               // B1: zeros visible

    // ---- 4) ballot-based stable rank (warps 0..5 hold the labels) ----
    int rank_in_warp = 0;
    if (tid < HW_) {
        unsigned pmask = (wid == 5) ? 0x0000FFFFu : 0xFFFFFFFFu;
        unsigned mm = __match_any_sync(pmask, mylbl) & pmask;
        rank_in_warp = __popc(mm & ((1u << lane) - 1u));
        if ((mm & ((1u << lane) - 1u)) == 0u)
            s_wcnt[wid * P_ + mylbl] = __popc(mm);
    }
    __syncthreads();                               // B2

    if (tid == 0) {                                // counts, inv, offsets, order
        int acc = 0;
        int cs[P_];
        #pragma unroll
        for (int p = 0; p < P_; p++) {
            int c = 0;
            #pragma unroll
            for (int w = 0; w < 6; w++) c += s_wcnt[w * P_ + p];
            cs[p] = c;
            s_cnt[p] = c;
            s_inv[p] = (c > 0) ? (1.0f / (float)c) : 0.0f;
            s_startW[p] = (unsigned char)acc;
            acc += (c + 3) >> 2;
        }
        unsigned char ord[P_];
        #pragma unroll
        for (int p = 0; p < P_; p++) ord[p] = (unsigned char)p;
        for (int i = 1; i < P_; i++) {
            unsigned char vv = ord[i]; int cv = cs[vv]; int j = i - 1;
            while (j >= 0 && cs[ord[j]] < cv) { ord[j + 1] = ord[j]; j--; }
            ord[j + 1] = vv;
        }
        #pragma unroll
        for (int p = 0; p < P_; p++) s_order[p] = ord[p];
    }
    __syncthreads();                               // B3

    unsigned char* pkb = (unsigned char*)s_pk;
    if (tid < HW_) {                               // scatter stable-ranked indices
        int r = rank_in_warp;
        #pragma unroll
        for (int w = 0; w < 5; w++)
            if (w < wid) r += s_wcnt[w * P_ + mylbl];
        pkb[(int)s_startW[mylbl] * 4 + r] = (unsigned char)tid;
    }
    __syncthreads();                               // B4

    if (tid < P_) {                                // pad tails to /4
        int c = s_cnt[tid];
        if (c > 0) {
            int base = (int)s_startW[tid] * 4;
            unsigned char last = pkb[base + c - 1];
            int e = (c + 3) & ~3;
            for (int j = c; j < e; j++) pkb[base + j] = last;
        }
    }

    // ---- 5) join: tile staged + prologue done ----
    cpa_wait0();
    __syncthreads();                               // B5

    // ---- 6) gather: warp = (big, small) part pair; lane = channel row ----
    const int pa = s_order[wid];
    const int pb = s_order[15 - wid];
    const float* trow = s_tile + lane * RSTF;

    #pragma unroll
    for (int pi = 0; pi < 2; pi++) {
        const int pp = pi ? pb : pa;
        const int c = s_cnt[pp];
        float r = 0.0f;
        if (c > 0) {
            const int st  = (int)s_startW[pp];
            const int W   = (c + 3) >> 2;
            const int pad = (W << 2) - c;
            const unsigned* __restrict__ pk = &s_pk[st];
            float sum = 0.0f, mx = NEG_FILL;
            for (int w = 0; w < W; w++) {
                unsigned iw = pk[w];                  // uniform -> broadcast
                float a0 = trow[iw & 255];
                float a1 = trow[(iw >> 8) & 255];
                float a2 = trow[(iw >> 16) & 255];
                float a3 = trow[iw >> 24];
                sum += (a0 + a1) + (a2 + a3);
                mx = fmaxf(fmaxf(a0, a1), fmaxf(fmaxf(a2, a3), mx));
            }
            if (pad) sum -= (float)pad * trow[pkb[st * 4 + c - 1]];
            r = sum * s_inv[pp] + mx;
        }
        s_res[lane * 17 + pp] = r;                    // conflict-free (17 odd)
    }
    __syncthreads();                                  // B6

    // ---- 7) coalesced output ----
    #pragma unroll
    for (int k = 0; k < 2; k++) {
        int chl = (tid >> 4) + 16 * k;
        int pp  = tid & 15;
        out[(((size_t)n_i * C_ + (chb + chl)) * S_ + s_i) * P_ + pp]
            = s_res[chl * 17 + pp];
    }
}

extern "C" void kernel_launch(void* const* d_in, const int* in_sizes, int n_in,
                              void* d_out, int out_size)
{
    const float* x    = (const float*)d_in[0];
    const int*   lbls = (const int*)d_in[1];
    float*       out  = (float*)d_out;

    dim3 grid(NS_, CGRPS);          // 512 x 8 = 4096 blocks, one launch
    hpp_kernel<<<grid, THREADS>>>(x, lbls, out);
}

// round 17
// speedup vs baseline: 3.0410x; 3.0410x over previous
#include <cuda_runtime.h>
#include <cuda_bf16.h>
#include <stdint.h>

// x: (16, 256, 32, 16, 11) fp32 ; part_labels: (16, 32, 16, 11) int64 (or int32)
// out: (16, 256, 32, 16) fp32
#define N_   16
#define C_   256
#define S_   32
#define HW_  176
#define P_   16
#define NS_  (N_ * S_)

#define THREADS  256
#define PREP_T   192               // 6 warps cover HW_=176 + 16 tail threads
#define CH_BLK   32
#define CGRPS    (C_ / CH_BLK)     // 8
#define RSTF     177               // odd -> conflict-free gather
#define NEG_FILL -100.0f

// compact per-ns metadata: 416 B
struct Meta {
    unsigned      pk[64];          // padded sorted byte indices, parts word-aligned
    unsigned char startW[16];      // word offset of each part's list in pk
    int           cnt[P_];
    float         inv[P_];
    unsigned char order[16];       // parts sorted by count desc
};
#define METAW (sizeof(Meta) / 4)   // 104 words

__device__ Meta g_meta[NS_];       // 213 KB static scratch

__device__ __forceinline__ void cpa4(uint32_t dst, const float* src) {
    asm volatile("cp.async.ca.shared.global [%0], [%1], 4;" :: "r"(dst), "l"(src));
}
__device__ __forceinline__ void cpa_commit() {
    asm volatile("cp.async.commit_group;");
}
__device__ __forceinline__ void cpa_wait0() {
    asm volatile("cp.async.wait_group 0;");
}

// ---------------- kernel 1: per-ns label metadata (compact) ----------------
__global__ __launch_bounds__(PREP_T)
void prep_kernel(const int* __restrict__ lbl32)
{
    __shared__ Meta sm;
    __shared__ int  s_wcnt[6 * P_];
    __shared__ int  s_is64;

    const int ns   = blockIdx.x;
    const int tid  = threadIdx.x;
    const int wid  = tid >> 5;
    const int lane = tid & 31;

    if (tid == 0) {
        int allz = 1;
        #pragma unroll
        for (int k = 0; k < 32; k++) allz &= (lbl32[2 * k + 1] == 0);
        s_is64 = allz;
    }
    if (tid < 6 * P_) s_wcnt[tid] = 0;
    if (tid < 64) sm.pk[tid] = 0u;          // deterministic padding
    __syncthreads();

    int mylbl = -1;
    if (tid < HW_) {
        int idx = ns * HW_ + tid;
        mylbl = s_is64 ? lbl32[2 * idx] : lbl32[idx];
    }

    // ballot-based stable rank (warps 0..5)
    int rank_in_warp = 0;
    if (tid < HW_) {
        unsigned pmask = (wid == 5) ? 0x0000FFFFu : 0xFFFFFFFFu;
        unsigned mm = __match_any_sync(pmask, mylbl) & pmask;
        rank_in_warp = __popc(mm & ((1u << lane) - 1u));
        if ((mm & ((1u << lane) - 1u)) == 0u)
            s_wcnt[wid * P_ + mylbl] = __popc(mm);
    }
    __syncthreads();

    if (tid >= HW_ && tid < HW_ + P_) {     // tail threads 176..191: counts
        int p = tid - HW_;
        int c = 0;
        #pragma unroll
        for (int w = 0; w < 6; w++) c += s_wcnt[w * P_ + p];
        sm.cnt[p] = c;
        sm.inv[p] = (c > 0) ? (1.0f / (float)c) : 0.0f;
    }
    __syncthreads();

    if (tid == 0) {                         // word offsets + balance order
        int acc = 0;
        #pragma unroll
        for (int p = 0; p < P_; p++) {
            sm.startW[p] = (unsigned char)acc;
            acc += (sm.cnt[p] + 3) >> 2;
        }
        unsigned char ord[P_];
        #pragma unroll
        for (int p = 0; p < P_; p++) ord[p] = (unsigned char)p;
        for (int i = 1; i < P_; i++) {
            unsigned char vv = ord[i]; int cv = sm.cnt[vv]; int j = i - 1;
            while (j >= 0 && sm.cnt[ord[j]] < cv) { ord[j + 1] = ord[j]; j--; }
            ord[j + 1] = vv;
        }
        #pragma unroll
        for (int p = 0; p < P_; p++) sm.order[p] = ord[p];
    }
    __syncthreads();

    // scatter stable-ranked indices into compact lists
    unsigned char* pkb = (unsigned char*)sm.pk;
    if (tid < HW_) {
        int r = rank_in_warp;
        #pragma unroll
        for (int w = 0; w < 5; w++)
            if (w < wid) r += s_wcnt[w * P_ + mylbl];
        pkb[(int)sm.startW[mylbl] * 4 + r] = (unsigned char)tid;
    }
    __syncthreads();

    if (tid < P_) {                         // pad tails with last index
        int c = sm.cnt[tid];
        if (c > 0) {
            int base = (int)sm.startW[tid] * 4;
            unsigned char last = pkb[base + c - 1];
            int e = (c + 3) & ~3;
            for (int j = c; j < e; j++) pkb[base + j] = last;
        }
    }
    __syncthreads();

    // coalesced smem -> global (104 words)
    const unsigned* s = (const unsigned*)&sm;
    unsigned* g = (unsigned*)&g_meta[ns];
    for (int i = tid; i < (int)METAW; i += PREP_T) g[i] = s[i];

    // PDL: allow the pool kernel to begin its meta-independent staging
    cudaTriggerProgrammaticLaunchCompletion();
}

// ---------------- kernel 2: stage + gather + store ----------------
struct PoolSM {
    Meta  m;
    float tile[CH_BLK * RSTF];    // 22.7 KB
    float res[CH_BLK * 17];
};

__global__ __launch_bounds__(THREADS, 8)
void pool_kernel(const float* __restrict__ x,
                 float*       __restrict__ out)
{
    __shared__ PoolSM sm;

    const int ns   = blockIdx.x;
    const int n_i  = ns >> 5;
    const int s_i  = ns & 31;
    const int chb  = blockIdx.y * CH_BLK;
    const int tid  = threadIdx.x;
    const int wid  = tid >> 5;
    const int lane = tid & 31;

    const float* xbase = x + (((size_t)n_i * C_ + chb) * S_ + s_i) * HW_;

    // 1) fire-and-forget tile staging (meta-independent -> runs under PDL overlap)
    #pragma unroll
    for (int r = 0; r < 4; r++) {
        const int row = wid * 4 + r;
        const float* src = xbase + (size_t)row * (S_ * HW_);
        uint32_t dsh = (uint32_t)__cvta_generic_to_shared(sm.tile + row * RSTF);
        #pragma unroll
        for (int k = 0; k < 6; k++) {
            int j = lane + 32 * k;
            if (j < HW_) cpa4(dsh + 4u * j, src + j);
        }
    }
    cpa_commit();

    // 2) wait until prep's meta writes are visible, then load meta (L2-hot)
    cudaGridDependencySynchronize();
    {
        const unsigned* g = (const unsigned*)&g_meta[ns];
        unsigned* s = (unsigned*)&sm.m;
        if (tid < (int)METAW) s[tid] = g[tid];
    }

    cpa_wait0();
    __syncthreads();

    // 3) gather: warp = (big, small) part pair; lane = channel row
    const unsigned char* pkb = (const unsigned char*)sm.m.pk;
    const int pa = sm.m.order[wid];
    const int pb = sm.m.order[15 - wid];
    const float* trow = sm.tile + lane * RSTF;

    #pragma unroll
    for (int pi = 0; pi < 2; pi++) {
        const int pp = pi ? pb : pa;
        const int c = sm.m.cnt[pp];
        float r = 0.0f;
        if (c > 0) {
            const int st  = (int)sm.m.startW[pp];
            const int W   = (c + 3) >> 2;
            const int pad = (W << 2) - c;
            const unsigned* __restrict__ pk = &sm.m.pk[st];
            float sum = 0.0f, mx = NEG_FILL;
            for (int w = 0; w < W; w++) {
                unsigned iw = pk[w];                  // uniform -> broadcast
                float a0 = trow[iw & 255];
                float a1 = trow[(iw >> 8) & 255];
                float a2 = trow[(iw >> 16) & 255];
                float a3 = trow[iw >> 24];
                sum += (a0 + a1) + (a2 + a3);
                mx = fmaxf(fmaxf(a0, a1), fmaxf(fmaxf(a2, a3), mx));
            }
            if (pad) sum -= (float)pad * trow[pkb[st * 4 + c - 1]];
            r = sum * sm.m.inv[pp] + mx;
        }
        sm.res[lane * 17 + pp] = r;                   // conflict-free (17 odd)
    }
    __syncthreads();

    // 4) coalesced output
    #pragma unroll
    for (int k = 0; k < 2; k++) {
        int chl = (tid >> 4) + 16 * k;
        int pp  = tid & 15;
        out[(((size_t)n_i * C_ + (chb + chl)) * S_ + s_i) * P_ + pp]
            = sm.res[chl * 17 + pp];
    }
}

extern "C" void kernel_launch(void* const* d_in, const int* in_sizes, int n_in,
                              void* d_out, int out_size)
{
    const float* x    = (const float*)d_in[0];
    const int*   lbls = (const int*)d_in[1];
    float*       out  = (float*)d_out;

    // kernel 1: normal launch
    prep_kernel<<<NS_, PREP_T>>>(lbls);

    // kernel 2: programmatic dependent launch — starts while prep drains;
    // cudaGridDependencySynchronize() inside gates the meta reads.
    cudaLaunchConfig_t cfg = {};
    cfg.gridDim  = dim3(NS_, CGRPS, 1);    // 512 x 8
    cfg.blockDim = dim3(THREADS, 1, 1);
    cfg.dynamicSmemBytes = 0;
    cudaLaunchAttribute attrs[1];
    attrs[0].id = cudaLaunchAttributeProgrammaticStreamSerialization;
    attrs[0].val.programmaticStreamSerializationAllowed = 1;
    cfg.attrs = attrs;
    cfg.numAttrs = 1;
    cudaLaunchKernelEx(&cfg, pool_kernel, x, out);
}